// round 4
// baseline (speedup 1.0000x reference)
#include <cuda_runtime.h>
#include <math.h>

// ---------------- static device scratch (allocation-free rule) ----------------
__device__ float g_w1q[320*192*25];
__device__ float g_w2q[192*192*25];
__device__ float g_w3q[192*192*25];
__device__ float g_w4q[192*3*25];
__device__ float g_b1q[192];
__device__ float g_b2q[192];
__device__ float g_b3q[192];
__device__ float g_b4q[3];
__device__ float g_a0[192*96*96];
__device__ float g_a1[192*192*192];
__device__ float g_a2[192*384*384];
__device__ float g_params[24];

typedef unsigned long long ull;

#define FMA_F32X2(d, a, b) \
    asm("fma.rn.f32x2 %0, %1, %2, %0;" : "+l"(d) : "l"(a), "l"(b))
#define PACK_F32X2(d, lo, hi) \
    asm("mov.b64 %0, {%1, %2};" : "=l"(d) : "f"(lo), "f"(hi))
#define UNPACK_F32X2(lo, hi, v) \
    asm("mov.b64 {%0, %1}, %2;" : "=f"(lo), "=f"(hi) : "l"(v))

// ---------------- weight/bias quantization: round-half-even ----------------
__global__ void quant_kernel(const float* __restrict__ src, float* __restrict__ dst, int n) {
    int i = blockIdx.x * blockDim.x + threadIdx.x;
    if (i < n) dst[i] = rintf(src[i]);
}

// ---------------- per-stage fixed-point parameters ----------------
__global__ void prep_kernel(const float* __restrict__ relus,
                            const int* __restrict__ dvds,
                            const int* __restrict__ bitsp) {
    if (threadIdx.x == 0 && blockIdx.x == 0) {
        float B = bitsp ? (float)(*bitsp) : 8.0f;
        float maxv = exp2f(B) - 1.0f;                  // 255
        const int sks[3] = {3, 4, 3};
        for (int i = 0; i < 3; i++) {
            float dv = (float)dvds[i];
            g_params[i*6+0] = exp2f(dv - 10.0f);               // addA = 2^(dv-1-9)
            g_params[i*6+1] = exp2f(9.0f - dv);                // invA = 2^-(dv-9)
            g_params[i*6+2] = rintf((maxv / relus[i]) * 33554432.0f); // clp
            float sk = (float)sks[i];
            g_params[i*6+3] = floorf((relus[i] + exp2f(sk - 1.0f)) * exp2f(-sk)); // scl
            g_params[i*6+4] = exp2f(24.0f - sk);               // addB = 2^(15+9-sk)
            g_params[i*6+5] = exp2f(sk - 25.0f);               // invB = 2^-(16+9-sk)
        }
        float dv3 = (float)dvds[3];
        g_params[18] = exp2f(dv3 - 9.0f);                      // stage3 addA
        g_params[19] = exp2f(8.0f - dv3);                      // stage3 invA
    }
}

// ---------------- universal transposed-conv (k=5,s=2,p=2,op=1) + quant epilogue ----
// Gather form: out(2y+py, 2x+px) = sum_ci sum_{dy,dx} in(y+dy, x+dx) * W[ci][co][...]
// FFMA2 version: output rows are processed in pairs (r, r+PH) packed into f32x2.
// Input tile staged in pair-slot layout: slots (2b, 2b+1) hold rows (b, b+PH)
// so each activation pair is one aligned LDS.64.
template<int COPB, int NYSUB>
__global__ void __launch_bounds__(256, 2) deconv_kernel(
    const float* __restrict__ in, float* __restrict__ out,
    const float* __restrict__ wq, const float* __restrict__ bq,
    const float* __restrict__ mul,
    int CIN, int COUT, int H, int W, int stage)
{
    constexpr int YPW   = 8 / NYSUB;       // input rows per warp
    constexpr int PH    = YPW / 2;         // pair offset
    constexpr int NSLOT = 2 * (10 - PH);   // pair slots per column
    constexpr int CST   = NSLOT + 2;       // padded column stride (even, conflict-free)

    __shared__ __align__(16) float sIn[8 * 34 * CST];
    __shared__ __align__(16) float sW[8][COPB][28];

    const int tid  = threadIdx.x;
    const int lane = tid & 31;
    const int wid  = tid >> 5;
    const int co_local = wid % COPB;
    const int ysub     = wid / COPB;
    const int x0   = blockIdx.x * 32;
    const int y0   = blockIdx.y * 8;
    const int co   = blockIdx.z * COPB + co_local;
    const int HW   = H * W;
    const int base = ysub * YPW;           // local base row for this warp

    ull acc2[PH][4];
    #pragma unroll
    for (int i = 0; i < PH; i++)
        #pragma unroll
        for (int j = 0; j < 4; j++) acc2[i][j] = 0ull;

    for (int cib = 0; cib < CIN; cib += 8) {
        __syncthreads();
        // stage input tile into pair-slot layout; rows y0-1..y0+8, OOB -> 0
        for (int idx = tid; idx < 8 * NSLOT * 34; idx += 256) {
            int c  = idx % 34;
            int t  = idx / 34;
            int s  = t % NSLOT;
            int ci = t / NSLOT;
            int row = (s & 1) ? (s >> 1) + PH : (s >> 1);
            int gy  = y0 - 1 + row;
            int gx  = x0 - 1 + c;
            float v = 0.f;
            if ((unsigned)gy < (unsigned)H && (unsigned)gx < (unsigned)W)
                v = in[(size_t)(cib + ci) * HW + (size_t)gy * W + gx];
            sIn[(ci * 34 + c) * CST + s] = v;
        }
        // stage weights [ci][co_local][25]
        for (int idx = tid; idx < 8 * COPB * 25; idx += 256) {
            int ci  = idx / (COPB * 25);
            int rem = idx - ci * (COPB * 25);
            int c8  = rem / 25;
            int t   = rem - c8 * 25;
            int gco = blockIdx.z * COPB + c8;
            sW[ci][c8][t] = (gco < COUT)
                ? wq[((size_t)(cib + ci) * COUT + gco) * 25 + t] : 0.f;
        }
        __syncthreads();

        if (co < COUT) {
            for (int ci = 0; ci < 8; ci++) {
                // duplicate 25 weights into f32x2 pairs
                const float4* wv = reinterpret_cast<const float4*>(&sW[ci][co_local][0]);
                float4 q0 = wv[0], q1 = wv[1], q2 = wv[2], q3 = wv[3], q4 = wv[4], q5 = wv[5];
                float wlast = sW[ci][co_local][24];
                ull wd[25];
                {
                    float wr[25] = {q0.x,q0.y,q0.z,q0.w, q1.x,q1.y,q1.z,q1.w,
                                    q2.x,q2.y,q2.z,q2.w, q3.x,q3.y,q3.z,q3.w,
                                    q4.x,q4.y,q4.z,q4.w, q5.x,q5.y,q5.z,q5.w, wlast};
                    #pragma unroll
                    for (int t = 0; t < 25; t++) PACK_F32X2(wd[t], wr[t], wr[t]);
                }

                const float* sInc = &sIn[ci * 34 * CST];
                // pair load: rows (base+b, base+b+PH) at col lane+dc
                #define PAIR_AT(b, dc) \
                    (*reinterpret_cast<const ull*>(&sInc[(lane + (dc)) * CST + 2 * (base + (b))]))

                ull P00 = PAIR_AT(0,0), P01 = PAIR_AT(0,1), P02 = PAIR_AT(0,2);
                ull P10 = PAIR_AT(1,0), P11 = PAIR_AT(1,1), P12 = PAIR_AT(1,2);
                ull P20 = PAIR_AT(2,0), P21 = PAIR_AT(2,1), P22 = PAIR_AT(2,2);

                #pragma unroll
                for (int p = 0; p < PH; p++) {
                    if (p) {
                        P00 = P10; P01 = P11; P02 = P12;
                        P10 = P20; P11 = P21; P12 = P22;
                        P20 = PAIR_AT(p+2, 0);
                        P21 = PAIR_AT(p+2, 1);
                        P22 = PAIR_AT(p+2, 2);
                    }
                    // (py=0,px=0): 9 taps
                    FMA_F32X2(acc2[p][0], P00, wd[24]);
                    FMA_F32X2(acc2[p][0], P01, wd[22]);
                    FMA_F32X2(acc2[p][0], P02, wd[20]);
                    FMA_F32X2(acc2[p][0], P10, wd[14]);
                    FMA_F32X2(acc2[p][0], P11, wd[12]);
                    FMA_F32X2(acc2[p][0], P12, wd[10]);
                    FMA_F32X2(acc2[p][0], P20, wd[4]);
                    FMA_F32X2(acc2[p][0], P21, wd[2]);
                    FMA_F32X2(acc2[p][0], P22, wd[0]);
                    // (py=0,px=1): 6 taps
                    FMA_F32X2(acc2[p][1], P01, wd[23]);
                    FMA_F32X2(acc2[p][1], P02, wd[21]);
                    FMA_F32X2(acc2[p][1], P11, wd[13]);
                    FMA_F32X2(acc2[p][1], P12, wd[11]);
                    FMA_F32X2(acc2[p][1], P21, wd[3]);
                    FMA_F32X2(acc2[p][1], P22, wd[1]);
                    // (py=1,px=0): 6 taps
                    FMA_F32X2(acc2[p][2], P10, wd[19]);
                    FMA_F32X2(acc2[p][2], P11, wd[17]);
                    FMA_F32X2(acc2[p][2], P12, wd[15]);
                    FMA_F32X2(acc2[p][2], P20, wd[9]);
                    FMA_F32X2(acc2[p][2], P21, wd[7]);
                    FMA_F32X2(acc2[p][2], P22, wd[5]);
                    // (py=1,px=1): 4 taps
                    FMA_F32X2(acc2[p][3], P11, wd[18]);
                    FMA_F32X2(acc2[p][3], P12, wd[16]);
                    FMA_F32X2(acc2[p][3], P21, wd[8]);
                    FMA_F32X2(acc2[p][3], P22, wd[6]);
                }
                #undef PAIR_AT
            }
        }
    }

    if (co >= COUT) return;
    const int x = x0 + lane;

    const float bias = bq[co];
    const float m    = mul[co];
    float addA, invA, clpv = 0.f, sclv = 0.f, addB = 0.f, invB = 0.f;
    if (stage < 3) {
        addA = g_params[stage*6+0]; invA = g_params[stage*6+1];
        clpv = g_params[stage*6+2]; sclv = g_params[stage*6+3];
        addB = g_params[stage*6+4]; invB = g_params[stage*6+5];
    } else {
        addA = g_params[18]; invA = g_params[19];
    }
    const int OW = 2 * W;
    #pragma unroll
    for (int p = 0; p < PH; p++) {
        #pragma unroll
        for (int q = 0; q < 4; q++) {
            int py = q >> 1, px = q & 1;
            float vL, vH;
            UNPACK_F32X2(vL, vH, acc2[p][q]);
            #pragma unroll
            for (int h = 0; h < 2; h++) {
                float v = (h == 0) ? vL : vH;
                int oy = 2 * (y0 + base + p + h * PH) + py;
                v = (v + bias) * m;
                v = floorf((v + addA) * invA);
                if (stage < 3) {
                    v = fminf(fmaxf(v, 0.f), clpv);
                    v = floorf((v * sclv + addB) * invB);
                } else {
                    v = v / 255.0f;
                }
                out[(size_t)co * (4 * HW) + (size_t)oy * OW + (2 * x + px)] = v;
            }
        }
    }
}

// ---------------- host launcher (graph-capturable: kernel launches only) -------
extern "C" void kernel_launch(void* const* d_in, const int* in_sizes, int n_in,
                              void* d_out, int out_size)
{
    const float* x     = (const float*)d_in[0];
    const float* w1    = (const float*)d_in[1];
    const float* b1    = (const float*)d_in[2];
    const float* w2    = (const float*)d_in[3];
    const float* b2    = (const float*)d_in[4];
    const float* w3    = (const float*)d_in[5];
    const float* b3    = (const float*)d_in[6];
    const float* w4    = (const float*)d_in[7];
    const float* b4    = (const float*)d_in[8];
    const float* m0    = (const float*)d_in[9];
    const float* m1    = (const float*)d_in[10];
    const float* m2    = (const float*)d_in[11];
    const float* m3    = (const float*)d_in[12];
    const float* relus = (const float*)d_in[13];
    const int*   dvds  = (const int*)d_in[14];
    const int*   bitsp = (n_in > 15) ? (const int*)d_in[15] : nullptr;

    float *w1q, *w2q, *w3q, *w4q, *b1q, *b2q, *b3q, *b4q, *a0, *a1, *a2;
    cudaGetSymbolAddress((void**)&w1q, g_w1q);
    cudaGetSymbolAddress((void**)&w2q, g_w2q);
    cudaGetSymbolAddress((void**)&w3q, g_w3q);
    cudaGetSymbolAddress((void**)&w4q, g_w4q);
    cudaGetSymbolAddress((void**)&b1q, g_b1q);
    cudaGetSymbolAddress((void**)&b2q, g_b2q);
    cudaGetSymbolAddress((void**)&b3q, g_b3q);
    cudaGetSymbolAddress((void**)&b4q, g_b4q);
    cudaGetSymbolAddress((void**)&a0,  g_a0);
    cudaGetSymbolAddress((void**)&a1,  g_a1);
    cudaGetSymbolAddress((void**)&a2,  g_a2);

    auto q = [](const float* s, float* d, int n) {
        quant_kernel<<<(n + 255) / 256, 256>>>(s, d, n);
    };
    q(w1, w1q, 320*192*25);
    q(w2, w2q, 192*192*25);
    q(w3, w3q, 192*192*25);
    q(w4, w4q, 192*3*25);
    q(b1, b1q, 192);
    q(b2, b2q, 192);
    q(b3, b3q, 192);
    q(b4, b4q, 3);
    prep_kernel<<<1, 1>>>(relus, dvds, bitsp);

    // L1: 320ch 48x48 -> 192ch 96x96
    deconv_kernel<8,1><<<dim3(2, 6, 24), 256>>>(x,  a0, w1q, b1q, m0, 320, 192,  48,  48, 0);
    // L2: 192ch 96x96 -> 192ch 192x192
    deconv_kernel<8,1><<<dim3(3, 12, 24), 256>>>(a0, a1, w2q, b2q, m1, 192, 192,  96,  96, 1);
    // L3: 192ch 192x192 -> 192ch 384x384
    deconv_kernel<8,1><<<dim3(6, 24, 24), 256>>>(a1, a2, w3q, b3q, m2, 192, 192, 192, 192, 2);
    // L4: 192ch 384x384 -> 3ch 768x768 (final quant + /255), 4 co-slots x 2 y-subtiles
    deconv_kernel<4,2><<<dim3(12, 48, 1), 256>>>(a2, (float*)d_out, w4q, b4q, m3, 192, 3, 384, 384, 3);
}

// round 5
// speedup vs baseline: 1.0030x; 1.0030x over previous
#include <cuda_runtime.h>
#include <math.h>

// ---------------- static device scratch (allocation-free rule) ----------------
__device__ float g_w1q[320*192*25];
__device__ float g_w2q[192*192*25];
__device__ float g_w3q[192*192*25];
__device__ float g_w4q[192*3*25];
__device__ float g_b1q[192];
__device__ float g_b2q[192];
__device__ float g_b3q[192];
__device__ float g_b4q[3];
__device__ float g_a0[192*96*96];
__device__ float g_a1[192*192*192];
__device__ float g_a2[192*384*384];
__device__ float g_params[24];

typedef unsigned long long ull;

#define FMA_F32X2(d, a, b) \
    asm("fma.rn.f32x2 %0, %1, %2, %0;" : "+l"(d) : "l"(a), "l"(b))
#define PACK_F32X2(d, lo, hi) \
    asm("mov.b64 %0, {%1, %2};" : "=l"(d) : "f"(lo), "f"(hi))
#define UNPACK_F32X2(lo, hi, v) \
    asm("mov.b64 {%0, %1}, %2;" : "=f"(lo), "=f"(hi) : "l"(v))

// ---------------- weight/bias quantization: round-half-even ----------------
__global__ void quant_kernel(const float* __restrict__ src, float* __restrict__ dst, int n) {
    int i = blockIdx.x * blockDim.x + threadIdx.x;
    if (i < n) dst[i] = rintf(src[i]);
}

// ---------------- per-stage fixed-point parameters ----------------
__global__ void prep_kernel(const float* __restrict__ relus,
                            const int* __restrict__ dvds,
                            const int* __restrict__ bitsp) {
    if (threadIdx.x == 0 && blockIdx.x == 0) {
        float B = bitsp ? (float)(*bitsp) : 8.0f;
        float maxv = exp2f(B) - 1.0f;                  // 255
        const int sks[3] = {3, 4, 3};
        for (int i = 0; i < 3; i++) {
            float dv = (float)dvds[i];
            g_params[i*6+0] = exp2f(dv - 10.0f);               // addA = 2^(dv-1-9)
            g_params[i*6+1] = exp2f(9.0f - dv);                // invA = 2^-(dv-9)
            g_params[i*6+2] = rintf((maxv / relus[i]) * 33554432.0f); // clp
            float sk = (float)sks[i];
            g_params[i*6+3] = floorf((relus[i] + exp2f(sk - 1.0f)) * exp2f(-sk)); // scl
            g_params[i*6+4] = exp2f(24.0f - sk);               // addB = 2^(15+9-sk)
            g_params[i*6+5] = exp2f(sk - 25.0f);               // invB = 2^-(16+9-sk)
        }
        float dv3 = (float)dvds[3];
        g_params[18] = exp2f(dv3 - 9.0f);                      // stage3 addA
        g_params[19] = exp2f(8.0f - dv3);                      // stage3 invA
    }
}

// ---------------- universal transposed-conv (k=5,s=2,p=2,op=1) + quant epilogue ----
// Gather form: out(2y+py, 2x+px) = sum_ci sum_{dy,dx} in(y+dy, x+dx) * W[ci][co][...]
// FFMA2 version: output rows are processed in pairs (r, r+PH) packed into f32x2.
// Input tile staged in pair-slot layout: slots (2b, 2b+1) hold rows (b, b+PH)
// so each activation pair is one aligned LDS.64.
template<int COPB, int NYSUB>
__global__ void __launch_bounds__(256, 2) deconv_kernel(
    const float* __restrict__ in, float* __restrict__ out,
    const float* __restrict__ wq, const float* __restrict__ bq,
    const float* __restrict__ mul,
    int CIN, int COUT, int H, int W, int stage)
{
    constexpr int YPW   = 8 / NYSUB;       // input rows per warp
    constexpr int PH    = YPW / 2;         // pair offset
    constexpr int NSLOT = 2 * (10 - PH);   // pair slots per column
    constexpr int CST   = NSLOT + 2;       // padded column stride (even, conflict-free)

    __shared__ __align__(16) float sIn[8 * 34 * CST];
    __shared__ __align__(16) float sW[8][COPB][28];

    const int tid  = threadIdx.x;
    const int lane = tid & 31;
    const int wid  = tid >> 5;
    const int co_local = wid % COPB;
    const int ysub     = wid / COPB;
    const int x0   = blockIdx.x * 32;
    const int y0   = blockIdx.y * 8;
    const int co   = blockIdx.z * COPB + co_local;
    const int HW   = H * W;
    const int base = ysub * YPW;           // local base row for this warp

    ull acc2[PH][4];
    #pragma unroll
    for (int i = 0; i < PH; i++)
        #pragma unroll
        for (int j = 0; j < 4; j++) acc2[i][j] = 0ull;

    for (int cib = 0; cib < CIN; cib += 8) {
        __syncthreads();
        // stage input tile into pair-slot layout; rows y0-1..y0+8, OOB -> 0
        for (int idx = tid; idx < 8 * NSLOT * 34; idx += 256) {
            int c  = idx % 34;
            int t  = idx / 34;
            int s  = t % NSLOT;
            int ci = t / NSLOT;
            int row = (s & 1) ? (s >> 1) + PH : (s >> 1);
            int gy  = y0 - 1 + row;
            int gx  = x0 - 1 + c;
            float v = 0.f;
            if ((unsigned)gy < (unsigned)H && (unsigned)gx < (unsigned)W)
                v = in[(size_t)(cib + ci) * HW + (size_t)gy * W + gx];
            sIn[(ci * 34 + c) * CST + s] = v;
        }
        // stage weights [ci][co_local][25]
        for (int idx = tid; idx < 8 * COPB * 25; idx += 256) {
            int ci  = idx / (COPB * 25);
            int rem = idx - ci * (COPB * 25);
            int c8  = rem / 25;
            int t   = rem - c8 * 25;
            int gco = blockIdx.z * COPB + c8;
            sW[ci][c8][t] = (gco < COUT)
                ? wq[((size_t)(cib + ci) * COUT + gco) * 25 + t] : 0.f;
        }
        __syncthreads();

        if (co < COUT) {
            for (int ci = 0; ci < 8; ci++) {
                // duplicate 25 weights into f32x2 pairs
                const float4* wv = reinterpret_cast<const float4*>(&sW[ci][co_local][0]);
                float4 q0 = wv[0], q1 = wv[1], q2 = wv[2], q3 = wv[3], q4 = wv[4], q5 = wv[5];
                float wlast = sW[ci][co_local][24];
                ull wd[25];
                {
                    float wr[25] = {q0.x,q0.y,q0.z,q0.w, q1.x,q1.y,q1.z,q1.w,
                                    q2.x,q2.y,q2.z,q2.w, q3.x,q3.y,q3.z,q3.w,
                                    q4.x,q4.y,q4.z,q4.w, q5.x,q5.y,q5.z,q5.w, wlast};
                    #pragma unroll
                    for (int t = 0; t < 25; t++) PACK_F32X2(wd[t], wr[t], wr[t]);
                }

                const float* sInc = &sIn[ci * 34 * CST];
                // pair load: rows (base+b, base+b+PH) at col lane+dc
                #define PAIR_AT(b, dc) \
                    (*reinterpret_cast<const ull*>(&sInc[(lane + (dc)) * CST + 2 * (base + (b))]))

                ull P00 = PAIR_AT(0,0), P01 = PAIR_AT(0,1), P02 = PAIR_AT(0,2);
                ull P10 = PAIR_AT(1,0), P11 = PAIR_AT(1,1), P12 = PAIR_AT(1,2);
                ull P20 = PAIR_AT(2,0), P21 = PAIR_AT(2,1), P22 = PAIR_AT(2,2);

                #pragma unroll
                for (int p = 0; p < PH; p++) {
                    if (p) {
                        P00 = P10; P01 = P11; P02 = P12;
                        P10 = P20; P11 = P21; P12 = P22;
                        P20 = PAIR_AT(p+2, 0);
                        P21 = PAIR_AT(p+2, 1);
                        P22 = PAIR_AT(p+2, 2);
                    }
                    // (py=0,px=0): 9 taps
                    FMA_F32X2(acc2[p][0], P00, wd[24]);
                    FMA_F32X2(acc2[p][0], P01, wd[22]);
                    FMA_F32X2(acc2[p][0], P02, wd[20]);
                    FMA_F32X2(acc2[p][0], P10, wd[14]);
                    FMA_F32X2(acc2[p][0], P11, wd[12]);
                    FMA_F32X2(acc2[p][0], P12, wd[10]);
                    FMA_F32X2(acc2[p][0], P20, wd[4]);
                    FMA_F32X2(acc2[p][0], P21, wd[2]);
                    FMA_F32X2(acc2[p][0], P22, wd[0]);
                    // (py=0,px=1): 6 taps
                    FMA_F32X2(acc2[p][1], P01, wd[23]);
                    FMA_F32X2(acc2[p][1], P02, wd[21]);
                    FMA_F32X2(acc2[p][1], P11, wd[13]);
                    FMA_F32X2(acc2[p][1], P12, wd[11]);
                    FMA_F32X2(acc2[p][1], P21, wd[3]);
                    FMA_F32X2(acc2[p][1], P22, wd[1]);
                    // (py=1,px=0): 6 taps
                    FMA_F32X2(acc2[p][2], P10, wd[19]);
                    FMA_F32X2(acc2[p][2], P11, wd[17]);
                    FMA_F32X2(acc2[p][2], P12, wd[15]);
                    FMA_F32X2(acc2[p][2], P20, wd[9]);
                    FMA_F32X2(acc2[p][2], P21, wd[7]);
                    FMA_F32X2(acc2[p][2], P22, wd[5]);
                    // (py=1,px=1): 4 taps
                    FMA_F32X2(acc2[p][3], P11, wd[18]);
                    FMA_F32X2(acc2[p][3], P12, wd[16]);
                    FMA_F32X2(acc2[p][3], P21, wd[8]);
                    FMA_F32X2(acc2[p][3], P22, wd[6]);
                }
                #undef PAIR_AT
            }
        }
    }

    if (co >= COUT) return;
    const int x = x0 + lane;

    const float bias = bq[co];
    const float m    = mul[co];
    float addA, invA, clpv = 0.f, sclv = 0.f, addB = 0.f, invB = 0.f;
    if (stage < 3) {
        addA = g_params[stage*6+0]; invA = g_params[stage*6+1];
        clpv = g_params[stage*6+2]; sclv = g_params[stage*6+3];
        addB = g_params[stage*6+4]; invB = g_params[stage*6+5];
    } else {
        addA = g_params[18]; invA = g_params[19];
    }
    const int OW = 2 * W;
    #pragma unroll
    for (int p = 0; p < PH; p++) {
        #pragma unroll
        for (int q = 0; q < 4; q++) {
            int py = q >> 1, px = q & 1;
            float vL, vH;
            UNPACK_F32X2(vL, vH, acc2[p][q]);
            #pragma unroll
            for (int h = 0; h < 2; h++) {
                float v = (h == 0) ? vL : vH;
                int oy = 2 * (y0 + base + p + h * PH) + py;
                v = (v + bias) * m;
                v = floorf((v + addA) * invA);
                if (stage < 3) {
                    v = fminf(fmaxf(v, 0.f), clpv);
                    v = floorf((v * sclv + addB) * invB);
                } else {
                    v = v / 255.0f;
                }
                out[(size_t)co * (4 * HW) + (size_t)oy * OW + (2 * x + px)] = v;
            }
        }
    }
}

// ---------------- host launcher (graph-capturable: kernel launches only) -------
extern "C" void kernel_launch(void* const* d_in, const int* in_sizes, int n_in,
                              void* d_out, int out_size)
{
    const float* x     = (const float*)d_in[0];
    const float* w1    = (const float*)d_in[1];
    const float* b1    = (const float*)d_in[2];
    const float* w2    = (const float*)d_in[3];
    const float* b2    = (const float*)d_in[4];
    const float* w3    = (const float*)d_in[5];
    const float* b3    = (const float*)d_in[6];
    const float* w4    = (const float*)d_in[7];
    const float* b4    = (const float*)d_in[8];
    const float* m0    = (const float*)d_in[9];
    const float* m1    = (const float*)d_in[10];
    const float* m2    = (const float*)d_in[11];
    const float* m3    = (const float*)d_in[12];
    const float* relus = (const float*)d_in[13];
    const int*   dvds  = (const int*)d_in[14];
    const int*   bitsp = (n_in > 15) ? (const int*)d_in[15] : nullptr;

    float *w1q, *w2q, *w3q, *w4q, *b1q, *b2q, *b3q, *b4q, *a0, *a1, *a2;
    cudaGetSymbolAddress((void**)&w1q, g_w1q);
    cudaGetSymbolAddress((void**)&w2q, g_w2q);
    cudaGetSymbolAddress((void**)&w3q, g_w3q);
    cudaGetSymbolAddress((void**)&w4q, g_w4q);
    cudaGetSymbolAddress((void**)&b1q, g_b1q);
    cudaGetSymbolAddress((void**)&b2q, g_b2q);
    cudaGetSymbolAddress((void**)&b3q, g_b3q);
    cudaGetSymbolAddress((void**)&b4q, g_b4q);
    cudaGetSymbolAddress((void**)&a0,  g_a0);
    cudaGetSymbolAddress((void**)&a1,  g_a1);
    cudaGetSymbolAddress((void**)&a2,  g_a2);

    auto q = [](const float* s, float* d, int n) {
        quant_kernel<<<(n + 255) / 256, 256>>>(s, d, n);
    };
    q(w1, w1q, 320*192*25);
    q(w2, w2q, 192*192*25);
    q(w3, w3q, 192*192*25);
    q(w4, w4q, 192*3*25);
    q(b1, b1q, 192);
    q(b2, b2q, 192);
    q(b3, b3q, 192);
    q(b4, b4q, 3);
    prep_kernel<<<1, 1>>>(relus, dvds, bitsp);

    // L1: 320ch 48x48 -> 192ch 96x96
    deconv_kernel<8,1><<<dim3(2, 6, 24), 256>>>(x,  a0, w1q, b1q, m0, 320, 192,  48,  48, 0);
    // L2: 192ch 96x96 -> 192ch 192x192
    deconv_kernel<8,1><<<dim3(3, 12, 24), 256>>>(a0, a1, w2q, b2q, m1, 192, 192,  96,  96, 1);
    // L3: 192ch 192x192 -> 192ch 384x384
    deconv_kernel<8,1><<<dim3(6, 24, 24), 256>>>(a1, a2, w3q, b3q, m2, 192, 192, 192, 192, 2);
    // L4: 192ch 384x384 -> 3ch 768x768 (final quant + /255), 4 co-slots x 2 y-subtiles
    deconv_kernel<4,2><<<dim3(12, 48, 1), 256>>>(a2, (float*)d_out, w4q, b4q, m3, 192, 3, 384, 384, 3);
}

// round 6
// speedup vs baseline: 7.7734x; 7.7500x over previous
#include <cuda_runtime.h>
#include <cuda_fp16.h>
#include <math.h>

typedef unsigned int u32;

// ---------------- static device scratch (allocation-free rule) ----------------
__device__ __half g_xh[48*48*320];          // L1 input NHWC fp16
__device__ __half g_h0[96*96*192];          // L1 out / L2 in
__device__ __half g_h1[192*192*192];        // L2 out / L3 in
__device__ __half g_h2[384*384*192];        // L3 out / L4 in
__device__ __half g_wt1[25*192*320];        // [tap][co][ci]
__device__ __half g_wt2[25*192*192];
__device__ __half g_wt3[25*192*192];
__device__ __half g_wt4[9*16*192];          // [tap][n=(parity*4+co)][ci]
__device__ float g_b1q[192];
__device__ float g_b2q[192];
__device__ float g_b3q[192];
__device__ float g_b4q[3];
__device__ float g_params[24];

// ---------------- PTX wrappers ----------------
#define CPASYNC(dst, src, sz) \
    asm volatile("cp.async.cg.shared.global [%0], [%1], 16, %2;" :: "r"(dst), "l"(src), "r"(sz))
#define CPCOMMIT() asm volatile("cp.async.commit_group;")
#define CPWAIT(n)  asm volatile("cp.async.wait_group %0;" :: "n"(n))
#define LDSM4(r0,r1,r2,r3,addr) \
    asm volatile("ldmatrix.sync.aligned.m8n8.x4.shared.b16 {%0,%1,%2,%3}, [%4];" \
        : "=r"(r0),"=r"(r1),"=r"(r2),"=r"(r3) : "r"(addr))
#define MMA16816(c0,c1,c2,c3,a0,a1,a2,a3,b0,b1) \
    asm volatile("mma.sync.aligned.m16n8k16.row.col.f32.f16.f16.f32 " \
        "{%0,%1,%2,%3}, {%4,%5,%6,%7}, {%8,%9}, {%0,%1,%2,%3};" \
        : "+f"(c0),"+f"(c1),"+f"(c2),"+f"(c3) \
        : "r"(a0),"r"(a1),"r"(a2),"r"(a3),"r"(b0),"r"(b1))

// ---------------- small prep kernels ----------------
__global__ void quant_kernel(const float* __restrict__ src, float* __restrict__ dst, int n) {
    int i = blockIdx.x * blockDim.x + threadIdx.x;
    if (i < n) dst[i] = rintf(src[i]);
}

__global__ void prep_kernel(const float* __restrict__ relus,
                            const int* __restrict__ dvds,
                            const int* __restrict__ bitsp) {
    if (threadIdx.x == 0 && blockIdx.x == 0) {
        float B = bitsp ? (float)(*bitsp) : 8.0f;
        float maxv = exp2f(B) - 1.0f;
        const int sks[3] = {3, 4, 3};
        for (int i = 0; i < 3; i++) {
            float dv = (float)dvds[i];
            g_params[i*6+0] = exp2f(dv - 10.0f);
            g_params[i*6+1] = exp2f(9.0f - dv);
            g_params[i*6+2] = rintf((maxv / relus[i]) * 33554432.0f);
            float sk = (float)sks[i];
            g_params[i*6+3] = floorf((relus[i] + exp2f(sk - 1.0f)) * exp2f(-sk));
            g_params[i*6+4] = exp2f(24.0f - sk);
            g_params[i*6+5] = exp2f(sk - 25.0f);
        }
        float dv3 = (float)dvds[3];
        g_params[18] = exp2f(dv3 - 9.0f);
        g_params[19] = exp2f(8.0f - dv3);
    }
}

// NCHW f32 -> NHWC fp16 (values are small ints: exact)
__global__ void nchw2nhwc(const float* __restrict__ src, __half* __restrict__ dst,
                          int C, int HW) {
    int idx = blockIdx.x * blockDim.x + threadIdx.x;
    if (idx >= C * HW) return;
    int s = idx / C, c = idx % C;
    dst[idx] = __float2half_rn(src[c * HW + s]);
}

// w [CIN][COUT][5][5] f32 -> wt [tap][co][ci] fp16 (rint-quantized)
__global__ void prep_w(const float* __restrict__ w, __half* __restrict__ wt,
                       int CIN, int COUT) {
    int idx = blockIdx.x * blockDim.x + threadIdx.x;
    if (idx >= CIN * COUT * 25) return;
    int ci = idx / (COUT * 25);
    int r  = idx % (COUT * 25);
    int co = r / 25;
    int t  = r % 25;
    wt[((size_t)t * COUT + co) * CIN + ci] = __float2half_rn(rintf(w[idx]));
}

// L4: w [192][3][5][5] -> wt4 [9][16][192], n=(py*2+px)*4+co, zeros for invalid/pad
__global__ void prep_w4(const float* __restrict__ w, __half* __restrict__ wt) {
    int idx = blockIdx.x * blockDim.x + threadIdx.x;
    if (idx >= 9 * 16 * 192) return;
    int t = idx / (16 * 192);
    int r = idx % (16 * 192);
    int n = r / 192;
    int ci = r % 192;
    int dy = t / 3 - 1, dx = t % 3 - 1;
    int p = n >> 2, co = n & 3;
    int py = p >> 1, px = p & 1;
    float v = 0.f;
    if (co < 3 && (py == 0 || dy >= 0) && (px == 0 || dx >= 0)) {
        int ky = py + 2 - 2 * dy, kx = px + 2 - 2 * dx;
        v = rintf(w[((size_t)ci * 3 + co) * 25 + ky * 5 + kx]);
    }
    wt[idx] = __float2half_rn(v);
}

// ---------------- tensor-core transposed conv ----------------
// CTA: 128 sites (8y x 16x) x NTILE output-n. 256 threads = 8 warps (WM x WN).
// A smem: [10 rows][18 cols][16 ci], site row padded to 48B. 2-stage ring (per ci-chunk).
// B smem: [NTILE n][16 ci], row padded to 48B. 4-stage ring (per k-iter), prefetch +3.
template<int NTILE, int WM, int WN, bool LAST>
__global__ void __launch_bounds__(256) conv_mma(
    const __half* __restrict__ inA, void* __restrict__ outp,
    const __half* __restrict__ Wt, const float* __restrict__ bq,
    const float* __restrict__ mul,
    int CIN, int COUT, int H, int W, int stage)
{
    constexpr int MI = 128 / (16 * WM);
    constexpr int NI = NTILE / (8 * WN);
    constexpr int NPAIR = NI / 2;
    constexpr int ASTG = 180 * 48;
    constexpr int BSTG = NTILE * 48;
    __shared__ __align__(16) char smem[2 * ASTG + 4 * BSTG];

    const int tid = threadIdx.x;
    const int lane = tid & 31, wid = tid >> 5;
    const int warp_m = wid % WM, warp_n = wid / WM;
    const int x0 = blockIdx.x * 16, y0 = blockIdx.y * 8;
    int py, px, co0;
    if (LAST) { py = 0; px = 0; co0 = 0; }
    else { py = blockIdx.z & 1; px = (blockIdx.z >> 1) & 1; co0 = (blockIdx.z >> 2) * 64; }

    // tap tables
    int ntaps, tAoff[9], tBrow[9];
    if (LAST) {
        ntaps = 9;
        #pragma unroll
        for (int t = 0; t < 9; t++) { tAoff[t] = ((t / 3) * 18 + (t % 3)) * 48; tBrow[t] = t * 16; }
    } else {
        ntaps = 0;
        for (int dy = (py ? 0 : -1); dy <= 1; dy++)
            for (int dx = (px ? 0 : -1); dx <= 1; dx++) {
                tAoff[ntaps] = ((dy + 1) * 18 + (dx + 1)) * 48;
                tBrow[ntaps] = ((py + 2 - 2 * dy) * 5 + (px + 2 - 2 * dx)) * COUT + co0;
                ntaps++;
            }
    }
    const int nchunks = CIN >> 4;
    const int niter = nchunks * ntaps;

    const u32 smem_u = (u32)__cvta_generic_to_shared(smem);
    const u32 Abase = smem_u;
    const u32 Bbase = smem_u + 2 * ASTG;

    auto loadA = [&](int chunk, int slot) {
        const int ci0 = chunk << 4;
        #pragma unroll
        for (int k = 0; k < 2; k++) {
            int idx = tid + k * 256;
            if (idx < 360) {
                int site = idx >> 1, seg = idx & 1;
                int r = site / 18, c = site % 18;
                int gy = y0 - 1 + r, gx = x0 - 1 + c;
                bool ok = (unsigned)gy < (unsigned)H && (unsigned)gx < (unsigned)W;
                const __half* src = ok ? (inA + ((size_t)(gy * W + gx) * CIN + ci0 + seg * 8)) : inA;
                u32 dst = Abase + slot * ASTG + site * 48 + seg * 16;
                CPASYNC(dst, src, ok ? 16 : 0);
            }
        }
    };
    auto loadB = [&](int tap, int chunk, int slot) {
        const int ci0 = chunk << 4;
        if (tid < NTILE * 2) {
            int n = tid >> 1, seg = tid & 1;
            const __half* src = Wt + (size_t)(tBrow[tap] + n) * CIN + ci0 + seg * 8;
            u32 dst = Bbase + slot * BSTG + n * 48 + seg * 16;
            CPASYNC(dst, src, 16);
        }
    };

    // prologue: A(0), B(0..2) in 3 groups (ntaps >= 4 so iters 0..2 are chunk 0)
    loadA(0, 0); loadB(0, 0, 0); CPCOMMIT();
    loadB(1, 0, 1); CPCOMMIT();
    loadB(2, 0, 2); CPCOMMIT();

    float acc[MI][NI][4];
    #pragma unroll
    for (int mi = 0; mi < MI; mi++)
        #pragma unroll
        for (int ni = 0; ni < NI; ni++)
            #pragma unroll
            for (int k = 0; k < 4; k++) acc[mi][ni][k] = 0.f;

    // per-lane ldmatrix address offsets
    const int la = lane & 7, ms = lane >> 3;
    const u32 aoff_lane = (u32)((la + ((ms & 1) << 3)) * 48 + ((ms >> 1) << 4));
    const u32 boff_lane = (u32)((la + ((lane >> 4) << 3)) * 48 + (((lane >> 3) & 1) << 4));

    int cur_tap = 0, cur_chunk = 0;
    int pf_tap = 3, pf_chunk = 0;   // metadata for iter i+3 (ntaps>=4 -> starts at tap 3, chunk 0)

    for (int i = 0; i < niter; i++) {
        CPWAIT(2);
        __syncthreads();
        // prefetch (after barrier: slot-cycle race-free)
        if (i + 3 < niter) loadB(pf_tap, pf_chunk, (i + 3) & 3);
        if (cur_tap == 0 && cur_chunk + 1 < nchunks) loadA(cur_chunk + 1, (cur_chunk + 1) & 1);
        CPCOMMIT();

        const u32 Astage = Abase + (cur_chunk & 1) * ASTG + tAoff[cur_tap] + aoff_lane;
        const u32 Bstage = Bbase + (i & 3) * BSTG + warp_n * (32 * 48) + boff_lane;

        u32 a[MI][4], b[NPAIR][4];
        #pragma unroll
        for (int mi = 0; mi < MI; mi++) {
            int ylocal = warp_m * MI + mi;
            LDSM4(a[mi][0], a[mi][1], a[mi][2], a[mi][3], Astage + ylocal * (18 * 48));
        }
        #pragma unroll
        for (int p2 = 0; p2 < NPAIR; p2++)
            LDSM4(b[p2][0], b[p2][1], b[p2][2], b[p2][3], Bstage + p2 * (16 * 48));

        #pragma unroll
        for (int mi = 0; mi < MI; mi++)
            #pragma unroll
            for (int ni = 0; ni < NI; ni++)
                MMA16816(acc[mi][ni][0], acc[mi][ni][1], acc[mi][ni][2], acc[mi][ni][3],
                         a[mi][0], a[mi][1], a[mi][2], a[mi][3],
                         b[ni >> 1][(ni & 1) * 2], b[ni >> 1][(ni & 1) * 2 + 1]);

        if (++cur_tap == ntaps) { cur_tap = 0; cur_chunk++; }
        if (++pf_tap == ntaps) { pf_tap = 0; pf_chunk++; }
    }
    CPWAIT(0);

    // -------- quant epilogue --------
    float addA, invA, clpv = 0.f, sclv = 0.f, addB = 0.f, invB = 0.f;
    if (!LAST) {
        addA = g_params[stage*6+0]; invA = g_params[stage*6+1];
        clpv = g_params[stage*6+2]; sclv = g_params[stage*6+3];
        addB = g_params[stage*6+4]; invB = g_params[stage*6+5];
    } else {
        addA = g_params[18]; invA = g_params[19];
    }
    const int W2 = 2 * W;

    if (!LAST) {
        __half* out = (__half*)outp;
        #pragma unroll
        for (int mi = 0; mi < MI; mi++) {
            int ylocal = warp_m * MI + mi;
            int oy = 2 * (y0 + ylocal) + py;
            #pragma unroll
            for (int ni = 0; ni < NI; ni++) {
                int co = co0 + warp_n * 32 + ni * 8 + (lane & 3) * 2;
                float b0f = bq[co], b1f = bq[co + 1];
                float m0f = mul[co], m1f = mul[co + 1];
                #pragma unroll
                for (int h = 0; h < 2; h++) {
                    int xl = (lane >> 2) + h * 8;
                    int ox = 2 * (x0 + xl) + px;
                    float v0 = acc[mi][ni][h * 2 + 0];
                    float v1 = acc[mi][ni][h * 2 + 1];
                    v0 = floorf(((v0 + b0f) * m0f + addA) * invA);
                    v0 = fminf(fmaxf(v0, 0.f), clpv);
                    v0 = floorf((v0 * sclv + addB) * invB);
                    v1 = floorf(((v1 + b1f) * m1f + addA) * invA);
                    v1 = fminf(fmaxf(v1, 0.f), clpv);
                    v1 = floorf((v1 * sclv + addB) * invB);
                    __half2 hv = __floats2half2_rn(v0, v1);
                    *(__half2*)(out + ((size_t)oy * W2 + ox) * COUT + co) = hv;
                }
            }
        }
    } else {
        float* out = (float*)outp;
        const int PLANE = W2 * 2 * H;   // 768*768
        #pragma unroll
        for (int ni = 0; ni < NI; ni++) {
            int nbase = ni * 8 + (lane & 3) * 2;
            #pragma unroll
            for (int h = 0; h < 2; h++) {
                int xl = (lane >> 2) + h * 8;
                #pragma unroll
                for (int j = 0; j < 2; j++) {
                    int n = nbase + j;
                    int p = n >> 2, c = n & 3;
                    if (c < 3) {
                        int pyy = p >> 1, pxx = p & 1;
                        int oy = 2 * (y0 + warp_m) + pyy;     // MI==1, ylocal=warp_m
                        int ox = 2 * (x0 + xl) + pxx;
                        float v = acc[0][ni][h * 2 + j];
                        v = (v + bq[c]) * mul[c];
                        v = floorf((v + addA) * invA);
                        out[(size_t)c * PLANE + (size_t)oy * W2 + ox] = v / 255.0f;
                    }
                }
            }
        }
    }
}

// ---------------- host launcher (graph-capturable: kernel launches only) -------
extern "C" void kernel_launch(void* const* d_in, const int* in_sizes, int n_in,
                              void* d_out, int out_size)
{
    const float* x     = (const float*)d_in[0];
    const float* w1    = (const float*)d_in[1];
    const float* b1    = (const float*)d_in[2];
    const float* w2    = (const float*)d_in[3];
    const float* b2    = (const float*)d_in[4];
    const float* w3    = (const float*)d_in[5];
    const float* b3    = (const float*)d_in[6];
    const float* w4    = (const float*)d_in[7];
    const float* b4    = (const float*)d_in[8];
    const float* m0    = (const float*)d_in[9];
    const float* m1    = (const float*)d_in[10];
    const float* m2    = (const float*)d_in[11];
    const float* m3    = (const float*)d_in[12];
    const float* relus = (const float*)d_in[13];
    const int*   dvds  = (const int*)d_in[14];
    const int*   bitsp = (n_in > 15) ? (const int*)d_in[15] : nullptr;

    __half *xh, *h0, *h1, *h2, *wt1, *wt2, *wt3, *wt4;
    float *b1q, *b2q, *b3q, *b4q;
    cudaGetSymbolAddress((void**)&xh,  g_xh);
    cudaGetSymbolAddress((void**)&h0,  g_h0);
    cudaGetSymbolAddress((void**)&h1,  g_h1);
    cudaGetSymbolAddress((void**)&h2,  g_h2);
    cudaGetSymbolAddress((void**)&wt1, g_wt1);
    cudaGetSymbolAddress((void**)&wt2, g_wt2);
    cudaGetSymbolAddress((void**)&wt3, g_wt3);
    cudaGetSymbolAddress((void**)&wt4, g_wt4);
    cudaGetSymbolAddress((void**)&b1q, g_b1q);
    cudaGetSymbolAddress((void**)&b2q, g_b2q);
    cudaGetSymbolAddress((void**)&b3q, g_b3q);
    cudaGetSymbolAddress((void**)&b4q, g_b4q);

    nchw2nhwc<<<(48*48*320 + 255)/256, 256>>>(x, xh, 320, 48*48);
    prep_w<<<(320*192*25 + 255)/256, 256>>>(w1, wt1, 320, 192);
    prep_w<<<(192*192*25 + 255)/256, 256>>>(w2, wt2, 192, 192);
    prep_w<<<(192*192*25 + 255)/256, 256>>>(w3, wt3, 192, 192);
    prep_w4<<<(9*16*192 + 255)/256, 256>>>(w4, wt4);
    quant_kernel<<<1, 192>>>(b1, b1q, 192);
    quant_kernel<<<1, 192>>>(b2, b2q, 192);
    quant_kernel<<<1, 192>>>(b3, b3q, 192);
    quant_kernel<<<1, 32>>>(b4, b4q, 3);
    prep_kernel<<<1, 1>>>(relus, dvds, bitsp);

    // L1: 320ch 48x48 -> 192ch 96x96
    conv_mma<64,4,2,false><<<dim3(3, 6, 12), 256>>>(xh, h0, wt1, b1q, m0, 320, 192, 48, 48, 0);
    // L2: 192ch 96x96 -> 192ch 192x192
    conv_mma<64,4,2,false><<<dim3(6, 12, 12), 256>>>(h0, h1, wt2, b2q, m1, 192, 192, 96, 96, 1);
    // L3: 192ch 192x192 -> 192ch 384x384
    conv_mma<64,4,2,false><<<dim3(12, 24, 12), 256>>>(h1, h2, wt3, b3q, m2, 192, 192, 192, 192, 2);
    // L4: 192ch 384x384 -> 3ch 768x768, parity-folded N=16, f32 NCHW out
    conv_mma<16,8,1,true><<<dim3(24, 48, 1), 256>>>(h2, d_out, wt4, b4q, m3, 192, 3, 384, 384, 3);
}

// round 7
// speedup vs baseline: 8.4071x; 1.0815x over previous
#include <cuda_runtime.h>
#include <cuda_fp16.h>
#include <math.h>

typedef unsigned int u32;

// ---------------- static device scratch (allocation-free rule) ----------------
__device__ __half g_xh[48*48*320];          // L1 input NHWC fp16
__device__ __half g_h0[96*96*192];          // L1 out / L2 in
__device__ __half g_h1[192*192*192];        // L2 out / L3 in
__device__ __half g_h2[384*384*192];        // L3 out / L4 in
__device__ __half g_wt1[25*192*320];        // [tap][co][ci]
__device__ __half g_wt2[25*192*192];
__device__ __half g_wt3[25*192*192];
__device__ __half g_wt4[9*16*192];          // [tap][n=(parity*4+co)][ci]
__device__ float g_b1q[192];
__device__ float g_b2q[192];
__device__ float g_b3q[192];
__device__ float g_b4q[3];
__device__ float g_params[24];

// ---------------- PTX wrappers ----------------
#define CPASYNC(dst, src, sz) \
    asm volatile("cp.async.cg.shared.global [%0], [%1], 16, %2;" :: "r"(dst), "l"(src), "r"(sz))
#define CPCOMMIT() asm volatile("cp.async.commit_group;")
#define CPWAIT(n)  asm volatile("cp.async.wait_group %0;" :: "n"(n))
#define LDSM4(r0,r1,r2,r3,addr) \
    asm volatile("ldmatrix.sync.aligned.m8n8.x4.shared.b16 {%0,%1,%2,%3}, [%4];" \
        : "=r"(r0),"=r"(r1),"=r"(r2),"=r"(r3) : "r"(addr))
#define MMA16816(c0,c1,c2,c3,a0,a1,a2,a3,b0,b1) \
    asm volatile("mma.sync.aligned.m16n8k16.row.col.f32.f16.f16.f32 " \
        "{%0,%1,%2,%3}, {%4,%5,%6,%7}, {%8,%9}, {%0,%1,%2,%3};" \
        : "+f"(c0),"+f"(c1),"+f"(c2),"+f"(c3) \
        : "r"(a0),"r"(a1),"r"(a2),"r"(a3),"r"(b0),"r"(b1))

// ---------------- small prep kernels ----------------
__global__ void quant_biases(const float* __restrict__ b1, const float* __restrict__ b2,
                             const float* __restrict__ b3, const float* __restrict__ b4) {
    int i = threadIdx.x;
    if (i < 192) {
        g_b1q[i] = rintf(b1[i]);
        g_b2q[i] = rintf(b2[i]);
        g_b3q[i] = rintf(b3[i]);
    }
    if (i < 3) g_b4q[i] = rintf(b4[i]);
}

__global__ void prep_kernel(const float* __restrict__ relus,
                            const int* __restrict__ dvds,
                            const int* __restrict__ bitsp) {
    if (threadIdx.x == 0 && blockIdx.x == 0) {
        float B = bitsp ? (float)(*bitsp) : 8.0f;
        float maxv = exp2f(B) - 1.0f;
        const int sks[3] = {3, 4, 3};
        for (int i = 0; i < 3; i++) {
            float dv = (float)dvds[i];
            g_params[i*6+0] = exp2f(dv - 10.0f);
            g_params[i*6+1] = exp2f(9.0f - dv);
            g_params[i*6+2] = rintf((maxv / relus[i]) * 33554432.0f);
            float sk = (float)sks[i];
            g_params[i*6+3] = floorf((relus[i] + exp2f(sk - 1.0f)) * exp2f(-sk));
            g_params[i*6+4] = exp2f(24.0f - sk);
            g_params[i*6+5] = exp2f(sk - 25.0f);
        }
        float dv3 = (float)dvds[3];
        g_params[18] = exp2f(dv3 - 9.0f);
        g_params[19] = exp2f(8.0f - dv3);
    }
}

// NCHW f32 -> NHWC fp16 (values are small ints: exact)
__global__ void nchw2nhwc(const float* __restrict__ src, __half* __restrict__ dst,
                          int C, int HW) {
    int idx = blockIdx.x * blockDim.x + threadIdx.x;
    if (idx >= C * HW) return;
    int s = idx / C, c = idx % C;
    dst[idx] = __float2half_rn(src[c * HW + s]);
}

// w [CIN][COUT][5][5] f32 -> wt [tap][co][ci] fp16, coalesced via smem transpose.
// One block per co: stage [CIN][25] slice, emit 25 contiguous half-rows of CIN.
__global__ void prep_w(const float* __restrict__ w, __half* __restrict__ wt,
                       int CIN, int COUT) {
    __shared__ float tile[320 * 25];
    const int co = blockIdx.x;
    const int tid = threadIdx.x;
    for (int i = tid; i < CIN * 25; i += 256) {
        int ci = i / 25, t = i % 25;
        tile[i] = w[((size_t)ci * COUT + co) * 25 + t];
    }
    __syncthreads();
    const int nc8 = CIN >> 3;
    for (int i = tid; i < 25 * nc8; i += 256) {
        int t = i / nc8, c8 = i % nc8;
        __half h[8];
        #pragma unroll
        for (int j = 0; j < 8; j++)
            h[j] = __float2half_rn(rintf(tile[(c8 * 8 + j) * 25 + t]));
        *(uint4*)(wt + ((size_t)t * COUT + co) * CIN + c8 * 8) = *(uint4*)h;
    }
}

// L4: w [192][3][5][5] -> wt4 [9][16][192], n=(py*2+px)*4+co, zeros for invalid/pad
__global__ void prep_w4(const float* __restrict__ w, __half* __restrict__ wt) {
    int idx = blockIdx.x * blockDim.x + threadIdx.x;
    if (idx >= 9 * 16 * 192) return;
    int t = idx / (16 * 192);
    int r = idx % (16 * 192);
    int n = r / 192;
    int ci = r % 192;
    int dy = t / 3 - 1, dx = t % 3 - 1;
    int p = n >> 2, co = n & 3;
    int py = p >> 1, px = p & 1;
    float v = 0.f;
    if (co < 3 && (py == 0 || dy >= 0) && (px == 0 || dx >= 0)) {
        int ky = py + 2 - 2 * dy, kx = px + 2 - 2 * dx;
        v = rintf(w[((size_t)ci * 3 + co) * 25 + ky * 5 + kx]);
    }
    wt[idx] = __float2half_rn(v);
}

// ---------------- tensor-core transposed conv ----------------
// CTA: (YR x 16) sites x NTILE output-n. 256 threads = 8 warps (WM x WN).
// A smem: [(YR+2) rows][18 cols][16 ci], site row padded to 48B. 2-stage ring.
// B smem: [NTILE n][16 ci], row padded to 48B. 4-stage ring, prefetch +3.
template<int NTILE, int WM, int WN, int YR, bool LAST>
__global__ void __launch_bounds__(256, 2) conv_mma(
    const __half* __restrict__ inA, void* __restrict__ outp,
    const __half* __restrict__ Wt, const float* __restrict__ bq,
    const float* __restrict__ mul,
    int CIN, int COUT, int H, int W, int stage)
{
    constexpr int MI = YR / WM;
    constexpr int NI = NTILE / (8 * WN);
    constexpr int NPAIR = NI / 2;
    constexpr int NSITES = (YR + 2) * 18;
    constexpr int ASTG = NSITES * 48;
    constexpr int BSTG = NTILE * 48;
    __shared__ __align__(16) char smem[2 * ASTG + 4 * BSTG];

    const int tid = threadIdx.x;
    const int lane = tid & 31, wid = tid >> 5;
    const int warp_m = wid % WM, warp_n = wid / WM;
    const int x0 = blockIdx.x * 16, y0 = blockIdx.y * YR;
    int py, px, co0;
    if (LAST) { py = 0; px = 0; co0 = 0; }
    else { py = blockIdx.z & 1; px = (blockIdx.z >> 1) & 1; co0 = (blockIdx.z >> 2) * 64; }

    // tap tables
    int ntaps, tAoff[9], tBrow[9];
    if (LAST) {
        ntaps = 9;
        #pragma unroll
        for (int t = 0; t < 9; t++) { tAoff[t] = ((t / 3) * 18 + (t % 3)) * 48; tBrow[t] = t * 16; }
    } else {
        ntaps = 0;
        for (int dy = (py ? 0 : -1); dy <= 1; dy++)
            for (int dx = (px ? 0 : -1); dx <= 1; dx++) {
                tAoff[ntaps] = ((dy + 1) * 18 + (dx + 1)) * 48;
                tBrow[ntaps] = ((py + 2 - 2 * dy) * 5 + (px + 2 - 2 * dx)) * COUT + co0;
                ntaps++;
            }
    }
    const int nchunks = CIN >> 4;
    const int niter = nchunks * ntaps;

    const u32 smem_u = (u32)__cvta_generic_to_shared(smem);
    const u32 Abase = smem_u;
    const u32 Bbase = smem_u + 2 * ASTG;

    auto loadA = [&](int chunk, int slot) {
        const int ci0 = chunk << 4;
        #pragma unroll
        for (int k = 0; k < (NSITES * 2 + 255) / 256; k++) {
            int idx = tid + k * 256;
            if (idx < NSITES * 2) {
                int site = idx >> 1, seg = idx & 1;
                int r = site / 18, c = site % 18;
                int gy = y0 - 1 + r, gx = x0 - 1 + c;
                bool ok = (unsigned)gy < (unsigned)H && (unsigned)gx < (unsigned)W;
                const __half* src = ok ? (inA + ((size_t)(gy * W + gx) * CIN + ci0 + seg * 8)) : inA;
                u32 dst = Abase + slot * ASTG + site * 48 + seg * 16;
                CPASYNC(dst, src, ok ? 16 : 0);
            }
        }
    };
    auto loadB = [&](int tap, int chunk, int slot) {
        const int ci0 = chunk << 4;
        if (tid < NTILE * 2) {
            int n = tid >> 1, seg = tid & 1;
            const __half* src = Wt + (size_t)(tBrow[tap] + n) * CIN + ci0 + seg * 8;
            u32 dst = Bbase + slot * BSTG + n * 48 + seg * 16;
            CPASYNC(dst, src, 16);
        }
    };

    // prologue: A(0), B(0..2) in 3 groups (ntaps >= 4 so iters 0..2 are chunk 0)
    loadA(0, 0); loadB(0, 0, 0); CPCOMMIT();
    loadB(1, 0, 1); CPCOMMIT();
    loadB(2, 0, 2); CPCOMMIT();

    float acc[MI][NI][4];
    #pragma unroll
    for (int mi = 0; mi < MI; mi++)
        #pragma unroll
        for (int ni = 0; ni < NI; ni++)
            #pragma unroll
            for (int k = 0; k < 4; k++) acc[mi][ni][k] = 0.f;

    // per-lane ldmatrix address offsets
    const int la = lane & 7, ms = lane >> 3;
    const u32 aoff_lane = (u32)((la + ((ms & 1) << 3)) * 48 + ((ms >> 1) << 4));
    const u32 boff_lane = (u32)((la + ((lane >> 4) << 3)) * 48 + (((lane >> 3) & 1) << 4));

    int cur_tap = 0, cur_chunk = 0;
    int pf_tap = 3, pf_chunk = 0;   // metadata for iter i+3 (ntaps>=4 -> starts at tap 3, chunk 0)

    for (int i = 0; i < niter; i++) {
        CPWAIT(2);
        __syncthreads();
        // prefetch (after barrier: slot-cycle race-free)
        if (i + 3 < niter) loadB(pf_tap, pf_chunk, (i + 3) & 3);
        if (cur_tap == 0 && cur_chunk + 1 < nchunks) loadA(cur_chunk + 1, (cur_chunk + 1) & 1);
        CPCOMMIT();

        const u32 Astage = Abase + (cur_chunk & 1) * ASTG + tAoff[cur_tap] + aoff_lane;
        const u32 Bstage = Bbase + (i & 3) * BSTG + warp_n * (32 * 48) + boff_lane;

        u32 a[MI][4], b[NPAIR][4];
        #pragma unroll
        for (int mi = 0; mi < MI; mi++) {
            int ylocal = warp_m * MI + mi;
            LDSM4(a[mi][0], a[mi][1], a[mi][2], a[mi][3], Astage + ylocal * (18 * 48));
        }
        #pragma unroll
        for (int p2 = 0; p2 < NPAIR; p2++)
            LDSM4(b[p2][0], b[p2][1], b[p2][2], b[p2][3], Bstage + p2 * (16 * 48));

        #pragma unroll
        for (int mi = 0; mi < MI; mi++)
            #pragma unroll
            for (int ni = 0; ni < NI; ni++)
                MMA16816(acc[mi][ni][0], acc[mi][ni][1], acc[mi][ni][2], acc[mi][ni][3],
                         a[mi][0], a[mi][1], a[mi][2], a[mi][3],
                         b[ni >> 1][(ni & 1) * 2], b[ni >> 1][(ni & 1) * 2 + 1]);

        if (++cur_tap == ntaps) { cur_tap = 0; cur_chunk++; }
        if (++pf_tap == ntaps) { pf_tap = 0; pf_chunk++; }
    }
    CPWAIT(0);

    // -------- quant epilogue --------
    float addA, invA, clpv = 0.f, sclv = 0.f, addB = 0.f, invB = 0.f;
    if (!LAST) {
        addA = g_params[stage*6+0]; invA = g_params[stage*6+1];
        clpv = g_params[stage*6+2]; sclv = g_params[stage*6+3];
        addB = g_params[stage*6+4]; invB = g_params[stage*6+5];
    } else {
        addA = g_params[18]; invA = g_params[19];
    }
    const int W2 = 2 * W;

    if (!LAST) {
        __half* out = (__half*)outp;
        #pragma unroll
        for (int mi = 0; mi < MI; mi++) {
            int ylocal = warp_m * MI + mi;
            int oy = 2 * (y0 + ylocal) + py;
            #pragma unroll
            for (int ni = 0; ni < NI; ni++) {
                int co = co0 + warp_n * 32 + ni * 8 + (lane & 3) * 2;
                float b0f = bq[co], b1f = bq[co + 1];
                float m0f = mul[co], m1f = mul[co + 1];
                #pragma unroll
                for (int h = 0; h < 2; h++) {
                    int xl = (lane >> 2) + h * 8;
                    int ox = 2 * (x0 + xl) + px;
                    float v0 = acc[mi][ni][h * 2 + 0];
                    float v1 = acc[mi][ni][h * 2 + 1];
                    v0 = floorf(((v0 + b0f) * m0f + addA) * invA);
                    v0 = fminf(fmaxf(v0, 0.f), clpv);
                    v0 = floorf((v0 * sclv + addB) * invB);
                    v1 = floorf(((v1 + b1f) * m1f + addA) * invA);
                    v1 = fminf(fmaxf(v1, 0.f), clpv);
                    v1 = floorf((v1 * sclv + addB) * invB);
                    __half2 hv = __floats2half2_rn(v0, v1);
                    *(__half2*)(out + ((size_t)oy * W2 + ox) * COUT + co) = hv;
                }
            }
        }
    } else {
        float* out = (float*)outp;
        const int PLANE = W2 * 2 * H;   // 768*768
        #pragma unroll
        for (int mi = 0; mi < MI; mi++) {
            int ylocal = warp_m * MI + mi;
            #pragma unroll
            for (int ni = 0; ni < NI; ni++) {
                int nbase = ni * 8 + (lane & 3) * 2;
                #pragma unroll
                for (int h = 0; h < 2; h++) {
                    int xl = (lane >> 2) + h * 8;
                    #pragma unroll
                    for (int j = 0; j < 2; j++) {
                        int n = nbase + j;
                        int p = n >> 2, c = n & 3;
                        if (c < 3) {
                            int pyy = p >> 1, pxx = p & 1;
                            int oy = 2 * (y0 + ylocal) + pyy;
                            int ox = 2 * (x0 + xl) + pxx;
                            float v = acc[mi][ni][h * 2 + j];
                            v = (v + bq[c]) * mul[c];
                            v = floorf((v + addA) * invA);
                            out[(size_t)c * PLANE + (size_t)oy * W2 + ox] = v / 255.0f;
                        }
                    }
                }
            }
        }
    }
}

// ---------------- host launcher (graph-capturable: kernel launches only) -------
extern "C" void kernel_launch(void* const* d_in, const int* in_sizes, int n_in,
                              void* d_out, int out_size)
{
    const float* x     = (const float*)d_in[0];
    const float* w1    = (const float*)d_in[1];
    const float* b1    = (const float*)d_in[2];
    const float* w2    = (const float*)d_in[3];
    const float* b2    = (const float*)d_in[4];
    const float* w3    = (const float*)d_in[5];
    const float* b3    = (const float*)d_in[6];
    const float* w4    = (const float*)d_in[7];
    const float* b4    = (const float*)d_in[8];
    const float* m0    = (const float*)d_in[9];
    const float* m1    = (const float*)d_in[10];
    const float* m2    = (const float*)d_in[11];
    const float* m3    = (const float*)d_in[12];
    const float* relus = (const float*)d_in[13];
    const int*   dvds  = (const int*)d_in[14];
    const int*   bitsp = (n_in > 15) ? (const int*)d_in[15] : nullptr;

    __half *xh, *h0, *h1, *h2, *wt1, *wt2, *wt3, *wt4;
    float *b1q, *b2q, *b3q, *b4q;
    cudaGetSymbolAddress((void**)&xh,  g_xh);
    cudaGetSymbolAddress((void**)&h0,  g_h0);
    cudaGetSymbolAddress((void**)&h1,  g_h1);
    cudaGetSymbolAddress((void**)&h2,  g_h2);
    cudaGetSymbolAddress((void**)&wt1, g_wt1);
    cudaGetSymbolAddress((void**)&wt2, g_wt2);
    cudaGetSymbolAddress((void**)&wt3, g_wt3);
    cudaGetSymbolAddress((void**)&wt4, g_wt4);
    cudaGetSymbolAddress((void**)&b1q, g_b1q);
    cudaGetSymbolAddress((void**)&b2q, g_b2q);
    cudaGetSymbolAddress((void**)&b3q, g_b3q);
    cudaGetSymbolAddress((void**)&b4q, g_b4q);

    nchw2nhwc<<<(48*48*320 + 255)/256, 256>>>(x, xh, 320, 48*48);
    prep_w<<<192, 256>>>(w1, wt1, 320, 192);
    prep_w<<<192, 256>>>(w2, wt2, 192, 192);
    prep_w<<<192, 256>>>(w3, wt3, 192, 192);
    prep_w4<<<(9*16*192 + 255)/256, 256>>>(w4, wt4);
    quant_biases<<<1, 256>>>(b1, b2, b3, b4);
    prep_kernel<<<1, 1>>>(relus, dvds, bitsp);

    // L1: 320ch 48x48 -> 192ch 96x96 (YR=8: keep grid wide enough)
    conv_mma<64,4,2,8,false><<<dim3(3, 6, 12), 256>>>(xh, h0, wt1, b1q, m0, 320, 192, 48, 48, 0);
    // L2: 192ch 96x96 -> 192ch 192x192
    conv_mma<64,4,2,16,false><<<dim3(6, 6, 12), 256>>>(h0, h1, wt2, b2q, m1, 192, 192, 96, 96, 1);
    // L3: 192ch 192x192 -> 192ch 384x384
    conv_mma<64,4,2,16,false><<<dim3(12, 12, 12), 256>>>(h1, h2, wt3, b3q, m2, 192, 192, 192, 192, 2);
    // L4: 192ch 384x384 -> 3ch 768x768, parity-folded N=16, f32 NCHW out
    conv_mma<16,8,1,16,true><<<dim3(24, 24, 1), 256>>>(h2, d_out, wt4, b4q, m3, 192, 3, 384, 384, 3);
}